// round 9
// baseline (speedup 1.0000x reference)
#include <cuda_runtime.h>
#include <cuda_fp16.h>
#include <math.h>
#include <stdint.h>

#define DMODEL 768
#define NH     8
#define DH     96
#define NLAYER 6
#define SPAN   512
#define SEQ    512
#define BATCH  8
#define PPOS   1024
#define FF     3072
#define NTOK   (BATCH*SEQ)
#define ZBAT   (BATCH*NH)
#define LN_EPS 1e-7f
#define NEGF   (-3.402823466e38f)
#define D3     (3*DMODEL)

// -------------------- scratch --------------------
__device__ float  g_h32 [NTOK*DMODEL];
__device__ __half g_h16 [NTOK*DMODEL];
__device__ __half g_qkv [(size_t)NTOK*D3];
__device__ __half g_ctx [NTOK*DMODEL];
__device__ __half g_tmp [NTOK*DMODEL];
__device__ __half g_wqkv[(size_t)NLAYER*DMODEL*D3];
__device__ float  g_bqkv[NLAYER*D3];
__device__ __half g_wi  [(size_t)NLAYER*DMODEL*FF];
__device__ __half g_wo2 [(size_t)NLAYER*FF*DMODEL];
__device__ __half g_wo  [(size_t)NLAYER*DMODEL*DMODEL];
__device__ __half g_wpk [(size_t)NLAYER*DMODEL*DMODEL];
__device__ __half g_wpq [(size_t)NLAYER*DMODEL*DMODEL];
__device__ __half g_rel [PPOS*DMODEL];
__device__ __half g_pk  [(size_t)NLAYER*PPOS*DMODEL];
__device__ __half g_pq  [(size_t)NLAYER*PPOS*DMODEL];
__device__ __half g_s1  [(size_t)ZBAT*SEQ*SEQ];
__device__ __half g_c2p [(size_t)ZBAT*SEQ*PPOS];
__device__ __half g_p2c [(size_t)ZBAT*SEQ*PPOS];
__device__ __half g_ffn [(size_t)NTOK*FF];

// -------------------- helpers --------------------
__device__ __forceinline__ float gelu_f(float x) {
    return 0.5f * x * (1.0f + erff(x * 0.7071067811865475f));
}
__device__ __forceinline__ uint32_t smem_u32(const void* p) {
    uint32_t a;
    asm("{ .reg .u64 t; cvta.to.shared.u64 t, %1; cvt.u32.u64 %0, t; }" : "=r"(a) : "l"(p));
    return a;
}
__device__ __forceinline__ void mma_f16(float c[4], const uint32_t a[4], const uint32_t b[2]) {
    asm volatile(
        "mma.sync.aligned.m16n8k16.row.col.f32.f16.f16.f32 "
        "{%0,%1,%2,%3},{%4,%5,%6,%7},{%8,%9},{%0,%1,%2,%3};\n"
        : "+f"(c[0]), "+f"(c[1]), "+f"(c[2]), "+f"(c[3])
        : "r"(a[0]), "r"(a[1]), "r"(a[2]), "r"(a[3]), "r"(b[0]), "r"(b[1]));
}
__device__ __forceinline__ void ldsm_x4(uint32_t r[4], uint32_t addr) {
    asm volatile("ldmatrix.sync.aligned.m8n8.x4.shared.b16 {%0,%1,%2,%3}, [%4];"
        : "=r"(r[0]), "=r"(r[1]), "=r"(r[2]), "=r"(r[3]) : "r"(addr));
}
__device__ __forceinline__ void ldsm_x4t(uint32_t r[4], uint32_t addr) {
    asm volatile("ldmatrix.sync.aligned.m8n8.x4.trans.shared.b16 {%0,%1,%2,%3}, [%4];"
        : "=r"(r[0]), "=r"(r[1]), "=r"(r[2]), "=r"(r[3]) : "r"(addr));
}
__device__ __forceinline__ void cp16(uint32_t dst, const void* src) {
    asm volatile("cp.async.cg.shared.global [%0], [%1], 16;" :: "r"(dst), "l"(src));
}
#define CP_COMMIT() asm volatile("cp.async.commit_group;" ::: "memory")
#define CP_WAIT2()  asm volatile("cp.async.wait_group 2;" ::: "memory")

// ============================ cp.async FP16 mma GEMM ============================
// C[M,N](f16) = A[M,K](f16) @ B(f16) + bias(f32, opt), opt gelu.
// BT=false: B is [K,N]. BT=true: B is [N,K]. BK=32 halfs, 4 smem stages.
template<int BM, int BN, int NWARP, bool BT>
__global__ void __launch_bounds__(NWARP*32, 2)
hgemm(const __half* __restrict__ A, const __half* __restrict__ B,
      const float* __restrict__ bias, __half* __restrict__ C,
      int K, int lda, int ldb, int ldc,
      long sAb, long sAh, long sBb, long sBh, long sBiasH,
      long sCb, long sCh, int act, int ntiles, int tpz, int tiles_x, int band)
{
    constexpr int THREADS = NWARP * 32;
    constexpr int WM = 64, WN = 32;
    constexpr int MI = WM / 16, NI = WN / 8;
    constexpr int WARPS_N = BN / WN;
    constexpr int ROWA = 80;                       // 32 halfs + 8 pad, bytes
    constexpr int ASTG = BM * ROWA;
    constexpr int ROWB = BT ? 80 : (BN + 8) * 2;
    constexpr int BSTG = BT ? (BN * 80) : (32 * ROWB);
    constexpr int ACH  = BM * 4;                   // 16B chunks per A stage
    constexpr int A_IT = (ACH + THREADS - 1) / THREADS;
    constexpr int BCHN = BN / 8;
    constexpr int BCH  = BT ? (BN * 4) : (32 * BCHN);
    constexpr int B_IT = (BCH + THREADS - 1) / THREADS;

    extern __shared__ char sm[];
    const uint32_t asb = smem_u32(sm);
    const uint32_t bsb = asb + 4 * ASTG;

    const int tid = threadIdx.x;
    const int wid = tid >> 5, lane = tid & 31;
    const int g = lane >> 2, tig = lane & 3;
    const int wm0 = (wid / WARPS_N) * WM, wn0 = (wid % WARPS_N) * WN;
    const int nk = K / 32;

    const uint32_t aoff = (uint32_t)(lane & 15) * ROWA + (uint32_t)(lane >> 4) * 16;
    const uint32_t boffT = ((uint32_t)(lane & 7) + (uint32_t)((lane >> 4) & 1) * 8) * 80
                         + (uint32_t)((lane >> 3) & 1) * 16;
    const uint32_t boffN = ((uint32_t)(lane & 7) + (uint32_t)((lane >> 3) & 1) * 8) * ROWB
                         + (uint32_t)((lane >> 4) & 1) * 16;

    for (int T = blockIdx.x; T < ntiles; T += gridDim.x) {
        const int z = T / tpz, tl = T - z * tpz;
        int ty, tx;
        if (band == 0) { ty = tl / tiles_x; tx = tl - ty * tiles_x; }
        else { ty = tl / 5; int rr = tl - ty * 5; tx = (band == 1 ? ty : 3 - ty) + rr; }
        const int m0 = ty * BM, n0 = tx * BN;
        const int bb = z >> 3, hh = z & 7;
        const __half* Az = A + (size_t)bb * sAb + (size_t)hh * sAh;
        const __half* Bz = B + (size_t)bb * sBb + (size_t)hh * sBh;
        __half* Cz = C + (size_t)bb * sCb + (size_t)hh * sCh;
        const float* biasp = bias ? (bias + (size_t)hh * sBiasH) : nullptr;

        float acc[MI][NI][4];
        #pragma unroll
        for (int i = 0; i < MI; i++)
            #pragma unroll
            for (int j = 0; j < NI; j++)
                #pragma unroll
                for (int t = 0; t < 4; t++) acc[i][j][t] = 0.f;

        auto issue = [&](int s) {
            if (s < nk) {
                const int k0 = s * 32;
                const uint32_t ab = asb + (s & 3) * ASTG;
                const uint32_t bbm = bsb + (s & 3) * BSTG;
                #pragma unroll
                for (int i = 0; i < A_IT; i++) {
                    int lin = tid + i * THREADS;
                    if ((ACH % THREADS == 0) || lin < ACH) {
                        int r = lin >> 2, c = lin & 3;
                        cp16(ab + (uint32_t)r * ROWA + (uint32_t)c * 16,
                             Az + (size_t)(m0 + r) * lda + k0 + c * 8);
                    }
                }
                #pragma unroll
                for (int i = 0; i < B_IT; i++) {
                    int lin = tid + i * THREADS;
                    if ((BCH % THREADS == 0) || lin < BCH) {
                        if (BT) {
                            int r = lin >> 2, c = lin & 3;
                            cp16(bbm + (uint32_t)r * 80 + (uint32_t)c * 16,
                                 Bz + (size_t)(n0 + r) * ldb + k0 + c * 8);
                        } else {
                            int kk = lin / BCHN, c = lin - kk * BCHN;
                            cp16(bbm + (uint32_t)kk * ROWB + (uint32_t)c * 16,
                                 Bz + (size_t)(k0 + kk) * ldb + n0 + c * 8);
                        }
                    }
                }
            }
            CP_COMMIT();
        };

        __syncthreads();               // previous tile's readers done before buffer reuse
        issue(0); issue(1); issue(2);
        int fetch = 3;

        for (int it = 0; it < nk; it++) {
            CP_WAIT2();
            __syncthreads();
            issue(fetch); fetch++;
            const int buf = it & 3;
            const uint32_t aB = asb + (uint32_t)buf * ASTG + (uint32_t)wm0 * ROWA + aoff;
            #pragma unroll
            for (int ks = 0; ks < 2; ks++) {
                uint32_t af[MI][4], bf[NI][2];
                #pragma unroll
                for (int i = 0; i < MI; i++)
                    ldsm_x4(af[i], aB + (uint32_t)i * (16 * ROWA) + (uint32_t)ks * 32);
                if (BT) {
                    const uint32_t bB = bsb + (uint32_t)buf * BSTG + (uint32_t)wn0 * 80 + boffT
                                      + (uint32_t)ks * 32;
                    #pragma unroll
                    for (int jj = 0; jj < NI / 2; jj++) {
                        uint32_t t4[4];
                        ldsm_x4(t4, bB + (uint32_t)jj * (16 * 80));
                        bf[2 * jj][0] = t4[0]; bf[2 * jj][1] = t4[1];
                        bf[2 * jj + 1][0] = t4[2]; bf[2 * jj + 1][1] = t4[3];
                    }
                } else {
                    const uint32_t bB = bsb + (uint32_t)buf * BSTG + (uint32_t)(ks * 16) * ROWB
                                      + boffN + (uint32_t)wn0 * 2;
                    #pragma unroll
                    for (int jj = 0; jj < NI / 2; jj++) {
                        uint32_t t4[4];
                        ldsm_x4t(t4, bB + (uint32_t)jj * 32);
                        bf[2 * jj][0] = t4[0]; bf[2 * jj][1] = t4[1];
                        bf[2 * jj + 1][0] = t4[2]; bf[2 * jj + 1][1] = t4[3];
                    }
                }
                #pragma unroll
                for (int i = 0; i < MI; i++)
                    #pragma unroll
                    for (int j = 0; j < NI; j++)
                        mma_f16(acc[i][j], af[i], bf[j]);
            }
        }

        // epilogue -> f16
        #pragma unroll
        for (int i = 0; i < MI; i++) {
            int r0 = m0 + wm0 + 16 * i + g;
            #pragma unroll
            for (int j = 0; j < NI; j++) {
                int col = n0 + wn0 + 8 * j + 2 * tig;
                float b0v = biasp ? biasp[col] : 0.f;
                float b1v = biasp ? biasp[col + 1] : 0.f;
                float v0 = acc[i][j][0] + b0v, v1 = acc[i][j][1] + b1v;
                float v2 = acc[i][j][2] + b0v, v3 = acc[i][j][3] + b1v;
                if (act == 1) { v0 = gelu_f(v0); v1 = gelu_f(v1); v2 = gelu_f(v2); v3 = gelu_f(v3); }
                *reinterpret_cast<__half2*>(Cz + (size_t)r0 * ldc + col) = __floats2half2_rn(v0, v1);
                *reinterpret_cast<__half2*>(Cz + (size_t)(r0 + 8) * ldc + col) = __floats2half2_rn(v2, v3);
            }
        }
    }
}

// -------------------- prologue converters --------------------
__global__ void cvt16(const float* __restrict__ in, __half* __restrict__ out, long n)
{
    long i = ((long)blockIdx.x * blockDim.x + threadIdx.x) * 4;
    if (i < n) {
        float4 v = *reinterpret_cast<const float4*>(in + i);
        out[i + 0] = __float2half(v.x);
        out[i + 1] = __float2half(v.y);
        out[i + 2] = __float2half(v.z);
        out[i + 3] = __float2half(v.w);
    }
}

__global__ void pack_qkv16(const float* __restrict__ Wq, const float* __restrict__ Wk,
                           const float* __restrict__ Wv, const float* __restrict__ bq,
                           const float* __restrict__ bk, const float* __restrict__ bv,
                           __half* __restrict__ W, float* __restrict__ b)
{
    long idx = (long)blockIdx.x * blockDim.x + threadIdx.x;
    const long totW = (long)NLAYER * DMODEL * D3;
    if (idx < totW) {
        int l = (int)(idx / ((long)DMODEL * D3));
        long r = idx - (long)l * DMODEL * D3;
        int row = (int)(r / D3);
        int col = (int)(r - (long)row * D3);
        const float* src; int c;
        if (col < DMODEL)        { src = Wq; c = col; }
        else if (col < 2*DMODEL) { src = Wk; c = col - DMODEL; }
        else                     { src = Wv; c = col - 2*DMODEL; }
        W[idx] = __float2half(src[((size_t)l * DMODEL + row) * DMODEL + c]);
    }
    if (idx < NLAYER * D3) {
        int l = (int)(idx / D3), col = (int)(idx - (long)l * D3);
        const float* src; int c;
        if (col < DMODEL)        { src = bq; c = col; }
        else if (col < 2*DMODEL) { src = bk; c = col - DMODEL; }
        else                     { src = bv; c = col - 2*DMODEL; }
        b[idx] = src[(size_t)l * DMODEL + c];
    }
}

// -------------------- block reductions (256 threads) --------------------
__device__ __forceinline__ float blk_sum256(float v) {
    __shared__ float sh[8];
    __syncthreads();
    for (int o = 16; o > 0; o >>= 1) v += __shfl_down_sync(0xffffffffu, v, o);
    if ((threadIdx.x & 31) == 0) sh[threadIdx.x >> 5] = v;
    __syncthreads();
    if (threadIdx.x == 0) {
        float s = 0.f;
        #pragma unroll
        for (int i = 0; i < 8; i++) s += sh[i];
        sh[0] = s;
    }
    __syncthreads();
    return sh[0];
}
__device__ __forceinline__ float blk_max256(float v) {
    __shared__ float sh[8];
    __syncthreads();
    for (int o = 16; o > 0; o >>= 1) v = fmaxf(v, __shfl_down_sync(0xffffffffu, v, o));
    if ((threadIdx.x & 31) == 0) sh[threadIdx.x >> 5] = v;
    __syncthreads();
    if (threadIdx.x == 0) {
        float s = sh[0];
        #pragma unroll
        for (int i = 1; i < 8; i++) s = fmaxf(s, sh[i]);
        sh[0] = s;
    }
    __syncthreads();
    return sh[0];
}

// ------------- combine rel-pos biases + mask + softmax (f16 in place) -----------
__global__ void combine_softmax(__half* __restrict__ s1, const __half* __restrict__ c2p,
                                const __half* __restrict__ p2c, const int* __restrict__ amask)
{
    const int q = blockIdx.x, z = blockIdx.y, b = z >> 3;
    const float inv_scale = 0.05892556509887896f;   // 1/sqrt(288)
    __half* srow = s1 + ((size_t)z * SEQ + q) * SEQ;
    const __half* crow = c2p + ((size_t)z * SEQ + q) * PPOS;
    const __half* pz   = p2c + (size_t)z * SEQ * PPOS;
    const int mq = amask[b * SEQ + q];
    float vals[2];
    #pragma unroll
    for (int i = 0; i < 2; i++) {
        int k = threadIdx.x + i * 256;
        int d = q - k + SPAN;
        float s = (__half2float(srow[k]) + __half2float(crow[d])
                 + __half2float(pz[(size_t)k * PPOS + d])) * inv_scale;
        int mk = amask[b * SEQ + k];
        vals[i] = (mq * mk > 0) ? s : NEGF;
    }
    float mx = blk_max256(fmaxf(vals[0], vals[1]));
    float e0 = __expf(vals[0] - mx), e1 = __expf(vals[1] - mx);
    float inv = 1.0f / blk_sum256(e0 + e1);
    srow[threadIdx.x]       = __float2half(e0 * inv);
    srow[threadIdx.x + 256] = __float2half(e1 * inv);
}

// ---------------- LayerNorm ----------------
__global__ void embed_ln(const float* __restrict__ x, const float* __restrict__ pos,
                         const float* __restrict__ g, const float* __restrict__ beta,
                         const int* __restrict__ amask, float* __restrict__ outF,
                         __half* __restrict__ outH)
{
    const int row = blockIdx.x, s = row & (SEQ - 1);
    float v[3], partial = 0.f;
    #pragma unroll
    for (int i = 0; i < 3; i++) {
        int j = threadIdx.x + i * 256;
        v[i] = x[(size_t)row * DMODEL + j] + pos[(size_t)s * DMODEL + j];
        partial += v[i];
    }
    float mean = blk_sum256(partial) * (1.0f / DMODEL);
    float p2 = 0.f;
    #pragma unroll
    for (int i = 0; i < 3; i++) { float d = v[i] - mean; p2 += d * d; }
    float rstd = rsqrtf(blk_sum256(p2) * (1.0f / DMODEL) + LN_EPS);
    float mf = (float)amask[row];
    #pragma unroll
    for (int i = 0; i < 3; i++) {
        int j = threadIdx.x + i * 256;
        float o = ((v[i] - mean) * rstd * g[j] + beta[j]) * mf;
        outF[(size_t)row * DMODEL + j] = o;
        outH[(size_t)row * DMODEL + j] = __float2half(o);
    }
}

__global__ void add_ln(const __half* __restrict__ a, const float* __restrict__ res,
                       const float* __restrict__ g, const float* __restrict__ beta,
                       float* __restrict__ outF, __half* __restrict__ outH)
{
    const int row = blockIdx.x;
    float v[3], partial = 0.f;
    #pragma unroll
    for (int i = 0; i < 3; i++) {
        int j = threadIdx.x + i * 256;
        v[i] = __half2float(a[(size_t)row * DMODEL + j]) + res[(size_t)row * DMODEL + j];
        partial += v[i];
    }
    float mean = blk_sum256(partial) * (1.0f / DMODEL);
    float p2 = 0.f;
    #pragma unroll
    for (int i = 0; i < 3; i++) { float d = v[i] - mean; p2 += d * d; }
    float rstd = rsqrtf(blk_sum256(p2) * (1.0f / DMODEL) + LN_EPS);
    #pragma unroll
    for (int i = 0; i < 3; i++) {
        int j = threadIdx.x + i * 256;
        float o = (v[i] - mean) * rstd * g[j] + beta[j];
        outF[(size_t)row * DMODEL + j] = o;
        outH[(size_t)row * DMODEL + j] = __float2half(o);
    }
}

// ==================================== launcher ====================================
static inline int pgrid(int tiles, int cap) { return tiles < cap ? tiles : cap; }

extern "C" void kernel_launch(void* const* d_in, const int* in_sizes, int n_in,
                              void* d_out, int out_size)
{
    const float* x       = (const float*)d_in[0];
    const float* pos_emb = (const float*)d_in[1];
    const float* rel_emb = (const float*)d_in[2];
    const float* ln_e_g  = (const float*)d_in[3];
    const float* ln_e_b  = (const float*)d_in[4];
    const float* Wq  = (const float*)d_in[5];
    const float* bq  = (const float*)d_in[6];
    const float* Wk  = (const float*)d_in[7];
    const float* bk  = (const float*)d_in[8];
    const float* Wv  = (const float*)d_in[9];
    const float* bv  = (const float*)d_in[10];
    const float* Wo  = (const float*)d_in[11];
    const float* bo  = (const float*)d_in[12];
    const float* Wpk = (const float*)d_in[13];
    const float* bpk = (const float*)d_in[14];
    const float* Wpq = (const float*)d_in[15];
    const float* bpq = (const float*)d_in[16];
    const float* ln1g = (const float*)d_in[17];
    const float* ln1b = (const float*)d_in[18];
    const float* Wi   = (const float*)d_in[19];
    const float* bi   = (const float*)d_in[20];
    const float* Wo2  = (const float*)d_in[21];
    const float* bo2  = (const float*)d_in[22];
    const float* ln2g = (const float*)d_in[23];
    const float* ln2b = (const float*)d_in[24];
    const int*   amask = (const int*)d_in[25];

    float *h32, *bqkv;
    __half *h16, *qkv, *ctx, *tmp, *wqkv, *wi, *wo2, *wo, *wpk, *wpq, *rel;
    __half *pk, *pq, *s1, *c2p, *p2c, *ffn;
    cudaGetSymbolAddress((void**)&h32,  g_h32);
    cudaGetSymbolAddress((void**)&h16,  g_h16);
    cudaGetSymbolAddress((void**)&qkv,  g_qkv);
    cudaGetSymbolAddress((void**)&ctx,  g_ctx);
    cudaGetSymbolAddress((void**)&tmp,  g_tmp);
    cudaGetSymbolAddress((void**)&wqkv, g_wqkv);
    cudaGetSymbolAddress((void**)&bqkv, g_bqkv);
    cudaGetSymbolAddress((void**)&wi,   g_wi);
    cudaGetSymbolAddress((void**)&wo2,  g_wo2);
    cudaGetSymbolAddress((void**)&wo,   g_wo);
    cudaGetSymbolAddress((void**)&wpk,  g_wpk);
    cudaGetSymbolAddress((void**)&wpq,  g_wpq);
    cudaGetSymbolAddress((void**)&rel,  g_rel);
    cudaGetSymbolAddress((void**)&pk,   g_pk);
    cudaGetSymbolAddress((void**)&pq,   g_pq);
    cudaGetSymbolAddress((void**)&s1,   g_s1);
    cudaGetSymbolAddress((void**)&c2p,  g_c2p);
    cudaGetSymbolAddress((void**)&p2c,  g_p2c);
    cudaGetSymbolAddress((void**)&ffn,  g_ffn);

    const long DD = (long)DMODEL * DMODEL;
    const long S2 = (long)SEQ * SEQ;
    const long SP = (long)SEQ * PPOS;
    const long SD3 = (long)SEQ * D3;
    const long PD = (long)PPOS * DMODEL;
    const int CAP = 296;

    // smem sizes: A 4*BM*80 + B stages
    const int SM_NN128 = 4 * 128 * 80 + 4 * 32 * 272;   // 75776
    const int SM_NT128 = 4 * 128 * 80 + 4 * 128 * 80;   // 81920
    const int SM_NN96  = 4 * 128 * 80 + 4 * 32 * 208;   // 67584
    cudaFuncSetAttribute(hgemm<128,128,8,false>, cudaFuncAttributeMaxDynamicSharedMemorySize, SM_NN128);
    cudaFuncSetAttribute(hgemm<128,128,8,true>,  cudaFuncAttributeMaxDynamicSharedMemorySize, SM_NT128);
    cudaFuncSetAttribute(hgemm<128,96,6,false>,  cudaFuncAttributeMaxDynamicSharedMemorySize, SM_NN96);

    // ---- prologue: weight conversion ----
    {
        long n;
        n = (long)NLAYER * DMODEL * D3;
        pack_qkv16<<<(unsigned)((n + 255) / 256), 256>>>(Wq, Wk, Wv, bq, bk, bv, wqkv, bqkv);
        n = (long)NLAYER * DMODEL * FF;
        cvt16<<<(unsigned)((n / 4 + 255) / 256), 256>>>(Wi, wi, n);
        cvt16<<<(unsigned)((n / 4 + 255) / 256), 256>>>(Wo2, wo2, n);
        n = (long)NLAYER * DD;
        cvt16<<<(unsigned)((n / 4 + 255) / 256), 256>>>(Wo, wo, n);
        cvt16<<<(unsigned)((n / 4 + 255) / 256), 256>>>(Wpk, wpk, n);
        cvt16<<<(unsigned)((n / 4 + 255) / 256), 256>>>(Wpq, wpq, n);
        n = (long)PPOS * DMODEL;
        cvt16<<<(unsigned)((n / 4 + 255) / 256), 256>>>(rel_emb, rel, n);
    }
    embed_ln<<<NTOK, 256>>>(x, pos_emb, ln_e_g, ln_e_b, amask, h32, h16);

    // pos projections, all layers (z = layer): 48 tiles/z
    hgemm<128,128,8,false><<<pgrid(288, CAP), 256, SM_NN128>>>(
        rel, wpk, bpk, pk, DMODEL, DMODEL, DMODEL, DMODEL,
        0, 0, 0, DD, DMODEL, 0, PD, 0, 288, 48, 6, 0);
    hgemm<128,128,8,false><<<pgrid(288, CAP), 256, SM_NN128>>>(
        rel, wpq, bpq, pq, DMODEL, DMODEL, DMODEL, DMODEL,
        0, 0, 0, DD, DMODEL, 0, PD, 0, 288, 48, 6, 0);

    for (int l = 0; l < NLAYER; l++) {
        // fused QKV: 576 tiles
        hgemm<128,128,8,false><<<pgrid(576, CAP), 256, SM_NN128>>>(
            h16, wqkv + (size_t)l * DMODEL * D3, bqkv + (size_t)l * D3, qkv,
            DMODEL, DMODEL, D3, D3, 0,0,0,0,0, 0,0, 0, 576, 576, 18, 0);

        // scores = Q @ K^T
        hgemm<128,128,8,true><<<pgrid(1024, CAP), 256, SM_NT128>>>(
            qkv, qkv + DMODEL, nullptr, s1, DH, D3, D3, SEQ,
            SD3, DH, SD3, DH, 0, 8*S2, S2, 0, 1024, 16, 4, 0);
        // c2p = Q @ PK^T (banded)
        hgemm<128,128,8,true><<<pgrid(1280, CAP), 256, SM_NT128>>>(
            qkv, pk + (size_t)l * PD, nullptr, c2p, DH, D3, DMODEL, PPOS,
            SD3, DH, 0, DH, 0, 8*SP, SP, 0, 1280, 20, 0, 1);
        // p2c = K @ PQ^T (banded)
        hgemm<128,128,8,true><<<pgrid(1280, CAP), 256, SM_NT128>>>(
            qkv + DMODEL, pq + (size_t)l * PD, nullptr, p2c, DH, D3, DMODEL, PPOS,
            SD3, DH, 0, DH, 0, 8*SP, SP, 0, 1280, 20, 0, 2);

        combine_softmax<<<dim3(SEQ, ZBAT), 256>>>(s1, c2p, p2c, amask);

        // ctx = probs @ V -> [b, q, h*96+d]
        hgemm<128,96,6,false><<<pgrid(256, CAP), 192, SM_NN96>>>(
            s1, qkv + 2*DMODEL, nullptr, ctx, SEQ, SEQ, D3, DMODEL,
            8*S2, S2, SD3, DH, 0, (long)SEQ*DMODEL, DH, 0, 256, 4, 1, 0);

        // attn out proj: 192 tiles
        hgemm<128,128,8,false><<<pgrid(192, CAP), 256, SM_NN128>>>(
            ctx, wo + (size_t)l*DD, bo + (size_t)l*DMODEL, tmp,
            DMODEL, DMODEL, DMODEL, DMODEL, 0,0,0,0,0, 0,0, 0, 192, 192, 6, 0);
        add_ln<<<NTOK, 256>>>(tmp, h32, ln1g + (size_t)l*DMODEL, ln1b + (size_t)l*DMODEL, h32, h16);

        // FFN1 (gelu): 768 tiles
        hgemm<128,128,8,false><<<pgrid(768, CAP), 256, SM_NN128>>>(
            h16, wi + (size_t)l*DMODEL*FF, bi + (size_t)l*FF, ffn,
            DMODEL, DMODEL, FF, FF, 0,0,0,0,0, 0,0, 1, 768, 768, 24, 0);
        // FFN2: K=3072, 192 tiles
        hgemm<128,128,8,false><<<pgrid(192, CAP), 256, SM_NN128>>>(
            ffn, wo2 + (size_t)l*FF*DMODEL, bo2 + (size_t)l*DMODEL, tmp,
            FF, FF, DMODEL, DMODEL, 0,0,0,0,0, 0,0, 0, 192, 192, 6, 0);

        float* outF = (l == NLAYER - 1) ? (float*)d_out : h32;
        add_ln<<<NTOK, 256>>>(tmp, h32, ln2g + (size_t)l*DMODEL, ln2b + (size_t)l*DMODEL, outF, h16);
    }
}

// round 10
// speedup vs baseline: 1.4160x; 1.4160x over previous
#include <cuda_runtime.h>
#include <cuda_fp16.h>
#include <math.h>
#include <stdint.h>

#define DMODEL 768
#define NH     8
#define DH     96
#define NLAYER 6
#define SPAN   512
#define SEQ    512
#define BATCH  8
#define PPOS   1024
#define FF     3072
#define NTOK   (BATCH*SEQ)
#define ZBAT   (BATCH*NH)
#define LN_EPS 1e-7f
#define NEGF   (-3.402823466e38f)
#define D3     (3*DMODEL)

// -------------------- scratch --------------------
__device__ float  g_h32 [NTOK*DMODEL];
__device__ __half g_h16 [NTOK*DMODEL];
__device__ __half g_qkv [(size_t)NTOK*D3];
__device__ __half g_ctx [NTOK*DMODEL];
__device__ __half g_tmp [NTOK*DMODEL];
__device__ __half g_wqkv[(size_t)NLAYER*DMODEL*D3];
__device__ float  g_bqkv[NLAYER*D3];
__device__ __half g_wi  [(size_t)NLAYER*DMODEL*FF];
__device__ __half g_wo2 [(size_t)NLAYER*FF*DMODEL];
__device__ __half g_wo  [(size_t)NLAYER*DMODEL*DMODEL];
__device__ __half g_wpk [(size_t)NLAYER*DMODEL*DMODEL];
__device__ __half g_wpq [(size_t)NLAYER*DMODEL*DMODEL];
__device__ __half g_rel [PPOS*DMODEL];
__device__ __half g_pk  [(size_t)NLAYER*PPOS*DMODEL];
__device__ __half g_pq  [(size_t)NLAYER*PPOS*DMODEL];
__device__ __half g_s1  [(size_t)ZBAT*SEQ*SEQ];
__device__ __half g_c2p [(size_t)ZBAT*SEQ*PPOS];
__device__ __half g_p2c [(size_t)ZBAT*SEQ*PPOS];
__device__ __half g_ffn [(size_t)NTOK*FF];

// -------------------- helpers --------------------
__device__ __forceinline__ float gelu_f(float x) {
    return 0.5f * x * (1.0f + erff(x * 0.7071067811865475f));
}
__device__ __forceinline__ uint32_t smem_u32(const void* p) {
    uint32_t a;
    asm("{ .reg .u64 t; cvta.to.shared.u64 t, %1; cvt.u32.u64 %0, t; }" : "=r"(a) : "l"(p));
    return a;
}
__device__ __forceinline__ void mma_f16(float c[4], const uint32_t a[4], const uint32_t b[2]) {
    asm volatile(
        "mma.sync.aligned.m16n8k16.row.col.f32.f16.f16.f32 "
        "{%0,%1,%2,%3},{%4,%5,%6,%7},{%8,%9},{%0,%1,%2,%3};\n"
        : "+f"(c[0]), "+f"(c[1]), "+f"(c[2]), "+f"(c[3])
        : "r"(a[0]), "r"(a[1]), "r"(a[2]), "r"(a[3]), "r"(b[0]), "r"(b[1]));
}
__device__ __forceinline__ void ldsm_x4(uint32_t r[4], uint32_t addr) {
    asm volatile("ldmatrix.sync.aligned.m8n8.x4.shared.b16 {%0,%1,%2,%3}, [%4];"
        : "=r"(r[0]), "=r"(r[1]), "=r"(r[2]), "=r"(r[3]) : "r"(addr));
}
__device__ __forceinline__ void ldsm_x4t(uint32_t r[4], uint32_t addr) {
    asm volatile("ldmatrix.sync.aligned.m8n8.x4.trans.shared.b16 {%0,%1,%2,%3}, [%4];"
        : "=r"(r[0]), "=r"(r[1]), "=r"(r[2]), "=r"(r[3]) : "r"(addr));
}
__device__ __forceinline__ void cp16(uint32_t dst, const void* src) {
    asm volatile("cp.async.cg.shared.global [%0], [%1], 16;" :: "r"(dst), "l"(src));
}
#define CP_COMMIT() asm volatile("cp.async.commit_group;" ::: "memory")
#define CP_WAIT2()  asm volatile("cp.async.wait_group 2;" ::: "memory")

// ============================ cp.async FP16 mma GEMM ============================
// C[M,N](f16) = A[M,K](f16) @ B(f16) + bias(f32, opt), opt gelu.
// BT=false: B is [K,N]. BT=true: B is [N,K]. BK=32 halfs, 4 smem stages.
// All per-chunk addresses hoisted: rolling gmem pointers + stage-base tables.
template<int BM, int BN, int NWARP, bool BT>
__global__ void __launch_bounds__(NWARP*32, 2)
hgemm(const __half* __restrict__ A, const __half* __restrict__ B,
      const float* __restrict__ bias, __half* __restrict__ C,
      int K, int lda, int ldb, int ldc,
      long sAb, long sAh, long sBb, long sBh, long sBiasH,
      long sCb, long sCh, int act, int ntiles, int tpz, int tiles_x, int band)
{
    constexpr int THREADS = NWARP * 32;
    constexpr int WM = 64, WN = 32;
    constexpr int MI = WM / 16, NI = WN / 8;
    constexpr int WARPS_N = BN / WN;
    constexpr int ROWA = 80;
    constexpr int ASTG = BM * ROWA;
    constexpr int ROWB = BT ? 80 : (BN + 8) * 2;
    constexpr int BSTG = BT ? (BN * 80) : (32 * ROWB);
    constexpr int ACH  = BM * 4;
    constexpr int A_IT = (ACH + THREADS - 1) / THREADS;
    constexpr int BCHN = BN / 8;
    constexpr int BCH  = BT ? (BN * 4) : (32 * BCHN);
    constexpr int B_IT = (BCH + THREADS - 1) / THREADS;

    extern __shared__ char sm[];
    const uint32_t asb = smem_u32(sm);
    const uint32_t bsb = asb + 4 * ASTG;

    const int tid = threadIdx.x;
    const int wid = tid >> 5, lane = tid & 31;
    const int g = lane >> 2, tig = lane & 3;
    const int wm0 = (wid / WARPS_N) * WM, wn0 = (wid % WARPS_N) * WN;
    const int nk = K / 32;
    const long bAdv = BT ? 32 : (long)32 * ldb;

    const uint32_t aoff = (uint32_t)(lane & 15) * ROWA + (uint32_t)(lane >> 4) * 16;
    const uint32_t boffT = ((uint32_t)(lane & 7) + (uint32_t)((lane >> 4) & 1) * 8) * 80
                         + (uint32_t)((lane >> 3) & 1) * 16;
    const uint32_t boffN = ((uint32_t)(lane & 7) + (uint32_t)((lane >> 3) & 1) * 8) * ROWB
                         + (uint32_t)((lane >> 4) & 1) * 16;

    for (int T = blockIdx.x; T < ntiles; T += gridDim.x) {
        const int z = T / tpz, tl = T - z * tpz;
        int ty, tx;
        if (band == 0) { ty = tl / tiles_x; tx = tl - ty * tiles_x; }
        else { ty = tl / 5; int rr = tl - ty * 5; tx = (band == 1 ? ty : 3 - ty) + rr; }
        const int m0 = ty * BM, n0 = tx * BN;
        const int bb = z >> 3, hh = z & 7;
        const __half* Az = A + (size_t)bb * sAb + (size_t)hh * sAh;
        const __half* Bz = B + (size_t)bb * sBb + (size_t)hh * sBh;
        __half* Cz = C + (size_t)bb * sCb + (size_t)hh * sCh;
        const float* biasp = bias ? (bias + (size_t)hh * sBiasH) : nullptr;

        // per-thread cp.async rolling sources + fixed smem dst offsets
        const __half* aS[A_IT]; uint32_t aD[A_IT];
        #pragma unroll
        for (int i = 0; i < A_IT; i++) {
            int lin = tid + i * THREADS;
            if ((ACH % THREADS == 0) || lin < ACH) {
                int r = lin >> 2, c = lin & 3;
                aS[i] = Az + (size_t)(m0 + r) * lda + c * 8;
                aD[i] = (uint32_t)r * ROWA + (uint32_t)c * 16;
            }
        }
        const __half* bS[B_IT]; uint32_t bD[B_IT];
        #pragma unroll
        for (int i = 0; i < B_IT; i++) {
            int lin = tid + i * THREADS;
            if ((BCH % THREADS == 0) || lin < BCH) {
                if (BT) {
                    int r = lin >> 2, c = lin & 3;
                    bS[i] = Bz + (size_t)(n0 + r) * ldb + c * 8;
                    bD[i] = (uint32_t)r * 80 + (uint32_t)c * 16;
                } else {
                    int kk = lin / BCHN, c = lin - kk * BCHN;
                    bS[i] = Bz + (size_t)kk * ldb + n0 + c * 8;
                    bD[i] = (uint32_t)kk * ROWB + (uint32_t)c * 16;
                }
            }
        }

        float acc[MI][NI][4];
        #pragma unroll
        for (int i = 0; i < MI; i++)
            #pragma unroll
            for (int j = 0; j < NI; j++)
                #pragma unroll
                for (int t = 0; t < 4; t++) acc[i][j][t] = 0.f;

        auto issue = [&](int s) {
            if (s < nk) {
                const uint32_t ab = asb + (s & 3) * ASTG;
                const uint32_t bbm = bsb + (s & 3) * BSTG;
                #pragma unroll
                for (int i = 0; i < A_IT; i++) {
                    int lin = tid + i * THREADS;
                    if ((ACH % THREADS == 0) || lin < ACH) {
                        cp16(ab + aD[i], aS[i]);
                        aS[i] += 32;
                    }
                }
                #pragma unroll
                for (int i = 0; i < B_IT; i++) {
                    int lin = tid + i * THREADS;
                    if ((BCH % THREADS == 0) || lin < BCH) {
                        cp16(bbm + bD[i], bS[i]);
                        bS[i] += bAdv;
                    }
                }
            }
            CP_COMMIT();
        };

        __syncthreads();               // previous tile's readers done before buffer reuse
        issue(0); issue(1); issue(2);
        int fetch = 3;

        // fragment-load stage bases (per buf)
        uint32_t aStg[4], bStg[4];
        #pragma unroll
        for (int b4 = 0; b4 < 4; b4++) {
            aStg[b4] = asb + (uint32_t)b4 * ASTG + (uint32_t)wm0 * ROWA + aoff;
            bStg[b4] = BT ? (bsb + (uint32_t)b4 * BSTG + (uint32_t)wn0 * 80 + boffT)
                          : (bsb + (uint32_t)b4 * BSTG + boffN + (uint32_t)wn0 * 2);
        }

        for (int it = 0; it < nk; it++) {
            CP_WAIT2();
            __syncthreads();
            issue(fetch); fetch++;
            const int buf = it & 3;
            const uint32_t aB = aStg[buf];
            const uint32_t bB = bStg[buf];
            #pragma unroll
            for (int ks = 0; ks < 2; ks++) {
                uint32_t af[MI][4], bf[NI][2];
                #pragma unroll
                for (int i = 0; i < MI; i++)
                    ldsm_x4(af[i], aB + (uint32_t)i * (16 * ROWA) + (uint32_t)ks * 32);
                if (BT) {
                    #pragma unroll
                    for (int jj = 0; jj < NI / 2; jj++) {
                        uint32_t t4[4];
                        ldsm_x4(t4, bB + (uint32_t)ks * 32 + (uint32_t)jj * (16 * 80));
                        bf[2 * jj][0] = t4[0]; bf[2 * jj][1] = t4[1];
                        bf[2 * jj + 1][0] = t4[2]; bf[2 * jj + 1][1] = t4[3];
                    }
                } else {
                    #pragma unroll
                    for (int jj = 0; jj < NI / 2; jj++) {
                        uint32_t t4[4];
                        ldsm_x4t(t4, bB + (uint32_t)(ks * 16) * ROWB + (uint32_t)jj * 32);
                        bf[2 * jj][0] = t4[0]; bf[2 * jj][1] = t4[1];
                        bf[2 * jj + 1][0] = t4[2]; bf[2 * jj + 1][1] = t4[3];
                    }
                }
                #pragma unroll
                for (int i = 0; i < MI; i++)
                    #pragma unroll
                    for (int j = 0; j < NI; j++)
                        mma_f16(acc[i][j], af[i], bf[j]);
            }
        }

        // epilogue -> f16
        #pragma unroll
        for (int i = 0; i < MI; i++) {
            int r0 = m0 + wm0 + 16 * i + g;
            #pragma unroll
            for (int j = 0; j < NI; j++) {
                int col = n0 + wn0 + 8 * j + 2 * tig;
                float b0v = biasp ? biasp[col] : 0.f;
                float b1v = biasp ? biasp[col + 1] : 0.f;
                float v0 = acc[i][j][0] + b0v, v1 = acc[i][j][1] + b1v;
                float v2 = acc[i][j][2] + b0v, v3 = acc[i][j][3] + b1v;
                if (act == 1) { v0 = gelu_f(v0); v1 = gelu_f(v1); v2 = gelu_f(v2); v3 = gelu_f(v3); }
                *reinterpret_cast<__half2*>(Cz + (size_t)r0 * ldc + col) = __floats2half2_rn(v0, v1);
                *reinterpret_cast<__half2*>(Cz + (size_t)(r0 + 8) * ldc + col) = __floats2half2_rn(v2, v3);
            }
        }
    }
}

// -------------------- prologue converters --------------------
__global__ void cvt16(const float* __restrict__ in, __half* __restrict__ out, long n)
{
    long i = ((long)blockIdx.x * blockDim.x + threadIdx.x) * 4;
    if (i < n) {
        float4 v = *reinterpret_cast<const float4*>(in + i);
        out[i + 0] = __float2half(v.x);
        out[i + 1] = __float2half(v.y);
        out[i + 2] = __float2half(v.z);
        out[i + 3] = __float2half(v.w);
    }
}

__global__ void pack_qkv16(const float* __restrict__ Wq, const float* __restrict__ Wk,
                           const float* __restrict__ Wv, const float* __restrict__ bq,
                           const float* __restrict__ bk, const float* __restrict__ bv,
                           __half* __restrict__ W, float* __restrict__ b)
{
    long idx = (long)blockIdx.x * blockDim.x + threadIdx.x;
    const long totW = (long)NLAYER * DMODEL * D3;
    if (idx < totW) {
        int l = (int)(idx / ((long)DMODEL * D3));
        long r = idx - (long)l * DMODEL * D3;
        int row = (int)(r / D3);
        int col = (int)(r - (long)row * D3);
        const float* src; int c;
        if (col < DMODEL)        { src = Wq; c = col; }
        else if (col < 2*DMODEL) { src = Wk; c = col - DMODEL; }
        else                     { src = Wv; c = col - 2*DMODEL; }
        W[idx] = __float2half(src[((size_t)l * DMODEL + row) * DMODEL + c]);
    }
    if (idx < NLAYER * D3) {
        int l = (int)(idx / D3), col = (int)(idx - (long)l * D3);
        const float* src; int c;
        if (col < DMODEL)        { src = bq; c = col; }
        else if (col < 2*DMODEL) { src = bk; c = col - DMODEL; }
        else                     { src = bv; c = col - 2*DMODEL; }
        b[idx] = src[(size_t)l * DMODEL + c];
    }
}

// -------------------- block reductions (256 threads) --------------------
__device__ __forceinline__ float blk_sum256(float v) {
    __shared__ float sh[8];
    __syncthreads();
    for (int o = 16; o > 0; o >>= 1) v += __shfl_down_sync(0xffffffffu, v, o);
    if ((threadIdx.x & 31) == 0) sh[threadIdx.x >> 5] = v;
    __syncthreads();
    if (threadIdx.x == 0) {
        float s = 0.f;
        #pragma unroll
        for (int i = 0; i < 8; i++) s += sh[i];
        sh[0] = s;
    }
    __syncthreads();
    return sh[0];
}
__device__ __forceinline__ float blk_max256(float v) {
    __shared__ float sh[8];
    __syncthreads();
    for (int o = 16; o > 0; o >>= 1) v = fmaxf(v, __shfl_down_sync(0xffffffffu, v, o));
    if ((threadIdx.x & 31) == 0) sh[threadIdx.x >> 5] = v;
    __syncthreads();
    if (threadIdx.x == 0) {
        float s = sh[0];
        #pragma unroll
        for (int i = 1; i < 8; i++) s = fmaxf(s, sh[i]);
        sh[0] = s;
    }
    __syncthreads();
    return sh[0];
}

// ------------- combine rel-pos biases + mask + softmax (f16 in place) -----------
__global__ void combine_softmax(__half* __restrict__ s1, const __half* __restrict__ c2p,
                                const __half* __restrict__ p2c, const int* __restrict__ amask)
{
    const int q = blockIdx.x, z = blockIdx.y, b = z >> 3;
    const float inv_scale = 0.05892556509887896f;   // 1/sqrt(288)
    __half* srow = s1 + ((size_t)z * SEQ + q) * SEQ;
    const __half* crow = c2p + ((size_t)z * SEQ + q) * PPOS;
    const __half* pz   = p2c + (size_t)z * SEQ * PPOS;
    const int mq = amask[b * SEQ + q];
    float vals[2];
    #pragma unroll
    for (int i = 0; i < 2; i++) {
        int k = threadIdx.x + i * 256;
        int d = q - k + SPAN;
        float s = (__half2float(srow[k]) + __half2float(crow[d])
                 + __half2float(pz[(size_t)k * PPOS + d])) * inv_scale;
        int mk = amask[b * SEQ + k];
        vals[i] = (mq * mk > 0) ? s : NEGF;
    }
    float mx = blk_max256(fmaxf(vals[0], vals[1]));
    float e0 = __expf(vals[0] - mx), e1 = __expf(vals[1] - mx);
    float inv = 1.0f / blk_sum256(e0 + e1);
    srow[threadIdx.x]       = __float2half(e0 * inv);
    srow[threadIdx.x + 256] = __float2half(e1 * inv);
}

// ---------------- LayerNorm ----------------
__global__ void embed_ln(const float* __restrict__ x, const float* __restrict__ pos,
                         const float* __restrict__ g, const float* __restrict__ beta,
                         const int* __restrict__ amask, float* __restrict__ outF,
                         __half* __restrict__ outH)
{
    const int row = blockIdx.x, s = row & (SEQ - 1);
    float v[3], partial = 0.f;
    #pragma unroll
    for (int i = 0; i < 3; i++) {
        int j = threadIdx.x + i * 256;
        v[i] = x[(size_t)row * DMODEL + j] + pos[(size_t)s * DMODEL + j];
        partial += v[i];
    }
    float mean = blk_sum256(partial) * (1.0f / DMODEL);
    float p2 = 0.f;
    #pragma unroll
    for (int i = 0; i < 3; i++) { float d = v[i] - mean; p2 += d * d; }
    float rstd = rsqrtf(blk_sum256(p2) * (1.0f / DMODEL) + LN_EPS);
    float mf = (float)amask[row];
    #pragma unroll
    for (int i = 0; i < 3; i++) {
        int j = threadIdx.x + i * 256;
        float o = ((v[i] - mean) * rstd * g[j] + beta[j]) * mf;
        outF[(size_t)row * DMODEL + j] = o;
        outH[(size_t)row * DMODEL + j] = __float2half(o);
    }
}

__global__ void add_ln(const __half* __restrict__ a, const float* __restrict__ res,
                       const float* __restrict__ g, const float* __restrict__ beta,
                       float* __restrict__ outF, __half* __restrict__ outH)
{
    const int row = blockIdx.x;
    float v[3], partial = 0.f;
    #pragma unroll
    for (int i = 0; i < 3; i++) {
        int j = threadIdx.x + i * 256;
        v[i] = __half2float(a[(size_t)row * DMODEL + j]) + res[(size_t)row * DMODEL + j];
        partial += v[i];
    }
    float mean = blk_sum256(partial) * (1.0f / DMODEL);
    float p2 = 0.f;
    #pragma unroll
    for (int i = 0; i < 3; i++) { float d = v[i] - mean; p2 += d * d; }
    float rstd = rsqrtf(blk_sum256(p2) * (1.0f / DMODEL) + LN_EPS);
    #pragma unroll
    for (int i = 0; i < 3; i++) {
        int j = threadIdx.x + i * 256;
        float o = (v[i] - mean) * rstd * g[j] + beta[j];
        outF[(size_t)row * DMODEL + j] = o;
        outH[(size_t)row * DMODEL + j] = __float2half(o);
    }
}

// ==================================== launcher ====================================
static inline int pgrid(int tiles, int cap) { return tiles < cap ? tiles : cap; }

extern "C" void kernel_launch(void* const* d_in, const int* in_sizes, int n_in,
                              void* d_out, int out_size)
{
    const float* x       = (const float*)d_in[0];
    const float* pos_emb = (const float*)d_in[1];
    const float* rel_emb = (const float*)d_in[2];
    const float* ln_e_g  = (const float*)d_in[3];
    const float* ln_e_b  = (const float*)d_in[4];
    const float* Wq  = (const float*)d_in[5];
    const float* bq  = (const float*)d_in[6];
    const float* Wk  = (const float*)d_in[7];
    const float* bk  = (const float*)d_in[8];
    const float* Wv  = (const float*)d_in[9];
    const float* bv  = (const float*)d_in[10];
    const float* Wo  = (const float*)d_in[11];
    const float* bo  = (const float*)d_in[12];
    const float* Wpk = (const float*)d_in[13];
    const float* bpk = (const float*)d_in[14];
    const float* Wpq = (const float*)d_in[15];
    const float* bpq = (const float*)d_in[16];
    const float* ln1g = (const float*)d_in[17];
    const float* ln1b = (const float*)d_in[18];
    const float* Wi   = (const float*)d_in[19];
    const float* bi   = (const float*)d_in[20];
    const float* Wo2  = (const float*)d_in[21];
    const float* bo2  = (const float*)d_in[22];
    const float* ln2g = (const float*)d_in[23];
    const float* ln2b = (const float*)d_in[24];
    const int*   amask = (const int*)d_in[25];

    float *h32, *bqkv;
    __half *h16, *qkv, *ctx, *tmp, *wqkv, *wi, *wo2, *wo, *wpk, *wpq, *rel;
    __half *pk, *pq, *s1, *c2p, *p2c, *ffn;
    cudaGetSymbolAddress((void**)&h32,  g_h32);
    cudaGetSymbolAddress((void**)&h16,  g_h16);
    cudaGetSymbolAddress((void**)&qkv,  g_qkv);
    cudaGetSymbolAddress((void**)&ctx,  g_ctx);
    cudaGetSymbolAddress((void**)&tmp,  g_tmp);
    cudaGetSymbolAddress((void**)&wqkv, g_wqkv);
    cudaGetSymbolAddress((void**)&bqkv, g_bqkv);
    cudaGetSymbolAddress((void**)&wi,   g_wi);
    cudaGetSymbolAddress((void**)&wo2,  g_wo2);
    cudaGetSymbolAddress((void**)&wo,   g_wo);
    cudaGetSymbolAddress((void**)&wpk,  g_wpk);
    cudaGetSymbolAddress((void**)&wpq,  g_wpq);
    cudaGetSymbolAddress((void**)&rel,  g_rel);
    cudaGetSymbolAddress((void**)&pk,   g_pk);
    cudaGetSymbolAddress((void**)&pq,   g_pq);
    cudaGetSymbolAddress((void**)&s1,   g_s1);
    cudaGetSymbolAddress((void**)&c2p,  g_c2p);
    cudaGetSymbolAddress((void**)&p2c,  g_p2c);
    cudaGetSymbolAddress((void**)&ffn,  g_ffn);

    const long DD = (long)DMODEL * DMODEL;
    const long S2 = (long)SEQ * SEQ;
    const long SP = (long)SEQ * PPOS;
    const long SD3 = (long)SEQ * D3;
    const long PD = (long)PPOS * DMODEL;
    const int CAP = 296;

    const int SM_NN128 = 4 * 128 * 80 + 4 * 32 * 272;   // 75776
    const int SM_NT128 = 4 * 128 * 80 + 4 * 128 * 80;   // 81920
    const int SM_NN96  = 4 * 128 * 80 + 4 * 32 * 208;   // 67584
    cudaFuncSetAttribute(hgemm<128,128,8,false>, cudaFuncAttributeMaxDynamicSharedMemorySize, SM_NN128);
    cudaFuncSetAttribute(hgemm<128,128,8,true>,  cudaFuncAttributeMaxDynamicSharedMemorySize, SM_NT128);
    cudaFuncSetAttribute(hgemm<128,96,6,false>,  cudaFuncAttributeMaxDynamicSharedMemorySize, SM_NN96);

    // ---- prologue: weight conversion ----
    {
        long n;
        n = (long)NLAYER * DMODEL * D3;
        pack_qkv16<<<(unsigned)((n + 255) / 256), 256>>>(Wq, Wk, Wv, bq, bk, bv, wqkv, bqkv);
        n = (long)NLAYER * DMODEL * FF;
        cvt16<<<(unsigned)((n / 4 + 255) / 256), 256>>>(Wi, wi, n);
        cvt16<<<(unsigned)((n / 4 + 255) / 256), 256>>>(Wo2, wo2, n);
        n = (long)NLAYER * DD;
        cvt16<<<(unsigned)((n / 4 + 255) / 256), 256>>>(Wo, wo, n);
        cvt16<<<(unsigned)((n / 4 + 255) / 256), 256>>>(Wpk, wpk, n);
        cvt16<<<(unsigned)((n / 4 + 255) / 256), 256>>>(Wpq, wpq, n);
        n = (long)PPOS * DMODEL;
        cvt16<<<(unsigned)((n / 4 + 255) / 256), 256>>>(rel_emb, rel, n);
    }
    embed_ln<<<NTOK, 256>>>(x, pos_emb, ln_e_g, ln_e_b, amask, h32, h16);

    // pos projections, all layers (z = layer): 48 tiles/z
    hgemm<128,128,8,false><<<pgrid(288, CAP), 256, SM_NN128>>>(
        rel, wpk, bpk, pk, DMODEL, DMODEL, DMODEL, DMODEL,
        0, 0, 0, DD, DMODEL, 0, PD, 0, 288, 48, 6, 0);
    hgemm<128,128,8,false><<<pgrid(288, CAP), 256, SM_NN128>>>(
        rel, wpq, bpq, pq, DMODEL, DMODEL, DMODEL, DMODEL,
        0, 0, 0, DD, DMODEL, 0, PD, 0, 288, 48, 6, 0);

    for (int l = 0; l < NLAYER; l++) {
        // fused QKV: 576 tiles
        hgemm<128,128,8,false><<<pgrid(576, CAP), 256, SM_NN128>>>(
            h16, wqkv + (size_t)l * DMODEL * D3, bqkv + (size_t)l * D3, qkv,
            DMODEL, DMODEL, D3, D3, 0,0,0,0,0, 0,0, 0, 576, 576, 18, 0);

        // scores = Q @ K^T
        hgemm<128,128,8,true><<<pgrid(1024, CAP), 256, SM_NT128>>>(
            qkv, qkv + DMODEL, nullptr, s1, DH, D3, D3, SEQ,
            SD3, DH, SD3, DH, 0, 8*S2, S2, 0, 1024, 16, 4, 0);
        // c2p = Q @ PK^T (banded)
        hgemm<128,128,8,true><<<pgrid(1280, CAP), 256, SM_NT128>>>(
            qkv, pk + (size_t)l * PD, nullptr, c2p, DH, D3, DMODEL, PPOS,
            SD3, DH, 0, DH, 0, 8*SP, SP, 0, 1280, 20, 0, 1);
        // p2c = K @ PQ^T (banded)
        hgemm<128,128,8,true><<<pgrid(1280, CAP), 256, SM_NT128>>>(
            qkv + DMODEL, pq + (size_t)l * PD, nullptr, p2c, DH, D3, DMODEL, PPOS,
            SD3, DH, 0, DH, 0, 8*SP, SP, 0, 1280, 20, 0, 2);

        combine_softmax<<<dim3(SEQ, ZBAT), 256>>>(s1, c2p, p2c, amask);

        // ctx = probs @ V -> [b, q, h*96+d]
        hgemm<128,96,6,false><<<pgrid(256, CAP), 192, SM_NN96>>>(
            s1, qkv + 2*DMODEL, nullptr, ctx, SEQ, SEQ, D3, DMODEL,
            8*S2, S2, SD3, DH, 0, (long)SEQ*DMODEL, DH, 0, 256, 4, 1, 0);

        // attn out proj: 192 tiles
        hgemm<128,128,8,false><<<pgrid(192, CAP), 256, SM_NN128>>>(
            ctx, wo + (size_t)l*DD, bo + (size_t)l*DMODEL, tmp,
            DMODEL, DMODEL, DMODEL, DMODEL, 0,0,0,0,0, 0,0, 0, 192, 192, 6, 0);
        add_ln<<<NTOK, 256>>>(tmp, h32, ln1g + (size_t)l*DMODEL, ln1b + (size_t)l*DMODEL, h32, h16);

        // FFN1 (gelu): 768 tiles
        hgemm<128,128,8,false><<<pgrid(768, CAP), 256, SM_NN128>>>(
            h16, wi + (size_t)l*DMODEL*FF, bi + (size_t)l*FF, ffn,
            DMODEL, DMODEL, FF, FF, 0,0,0,0,0, 0,0, 1, 768, 768, 24, 0);
        // FFN2: K=3072, 192 tiles
        hgemm<128,128,8,false><<<pgrid(192, CAP), 256, SM_NN128>>>(
            ffn, wo2 + (size_t)l*FF*DMODEL, bo2 + (size_t)l*DMODEL, tmp,
            FF, FF, DMODEL, DMODEL, 0,0,0,0,0, 0,0, 0, 192, 192, 6, 0);

        float* outF = (l == NLAYER - 1) ? (float*)d_out : h32;
        add_ln<<<NTOK, 256>>>(tmp, h32, ln2g + (size_t)l*DMODEL, ln2b + (size_t)l*DMODEL, outF, h16);
    }
}